// round 2
// baseline (speedup 1.0000x reference)
#include <cuda_runtime.h>
#include <cuda_bf16.h>
#include <cstdint>

#define NROWS 8192
#define DDIM  64
#define NCLS  100
#define EPSV  1e-6f

#define TI 128        // threads per block == i-rows per block
#define TJ 128        // j rows staged in shared per tile
#define JCHUNKS 16    // j-range splits (grid.y)
#define JPER (NROWS / JCHUNKS)   // 512

// Scratch (device globals; no allocation allowed).
// Partials are written exactly once per (i, chunk) -> fully deterministic.
__device__ float g_spos[NROWS * JCHUNKS];
__device__ float g_sneg[NROWS * JCHUNKS];
__device__ int   g_cnt[NCLS];

static __device__ __forceinline__ unsigned long long fadd2(unsigned long long a,
                                                           unsigned long long b) {
    unsigned long long r;
    asm("add.rn.f32x2 %0, %1, %2;" : "=l"(r) : "l"(a), "l"(b));
    return r;
}

static __device__ __forceinline__ float frcp(float x) {
    float r;
    asm("rcp.approx.f32 %0, %1;" : "=f"(r) : "f"(x));
    return r;
}

__global__ void ecstfl_count_kernel(const int* __restrict__ lab) {
    int t = blockIdx.x * blockDim.x + threadIdx.x;
    if (t < NCLS) g_cnt[t] = 0;           // zero first wave... see grid-sync note below
}

__global__ void ecstfl_count2_kernel(const int* __restrict__ lab) {
    int t = blockIdx.x * blockDim.x + threadIdx.x;
    if (t < NROWS) atomicAdd(&g_cnt[lab[t]], 1);
}

__global__ void __launch_bounds__(TI, 4)
ecstfl_main_kernel(const float* __restrict__ X, const int* __restrict__ lab) {
    __shared__ float shx[TJ * DDIM];   // negated x_j tile
    __shared__ int   shl[TJ];

    const int i  = blockIdx.x * TI + threadIdx.x;
    const int j0 = blockIdx.y * JPER;

    // Load my row x_i into registers as 32 packed f32x2 values.
    unsigned long long xi[DDIM / 2];
    {
        const ulonglong2* xrow = (const ulonglong2*)(X + (size_t)i * DDIM);
        #pragma unroll
        for (int q = 0; q < DDIM / 4; q++) {
            ulonglong2 v = xrow[q];
            xi[2 * q]     = v.x;
            xi[2 * q + 1] = v.y;
        }
    }
    const int myl = lab[i];

    const unsigned long long ABS2 = 0x7FFFFFFF7FFFFFFFULL;

    float sp = 0.0f;   // sum of dist over same-label j in this chunk
    float sn = 0.0f;   // sum of 1/(dist+eps) over diff-label j in this chunk

    #pragma unroll 1
    for (int t = 0; t < JPER / TJ; t++) {
        const int jt = j0 + t * TJ;

        __syncthreads();   // protect previous tile from overwrite

        // Stage TJ*DDIM floats (negated) cooperatively: 16 float4 per thread.
        {
            const float4* src = (const float4*)(X + (size_t)jt * DDIM);
            float4* dst = (float4*)shx;
            #pragma unroll
            for (int r = 0; r < (TJ * DDIM / 4) / TI; r++) {
                float4 v = src[threadIdx.x + r * TI];
                v.x = -v.x; v.y = -v.y; v.z = -v.z; v.w = -v.w;
                dst[threadIdx.x + r * TI] = v;
            }
            if (threadIdx.x < TJ) shl[threadIdx.x] = lab[jt + threadIdx.x];
        }
        __syncthreads();

        #pragma unroll 4
        for (int jl = 0; jl < TJ; jl++) {
            const ulonglong2* row = (const ulonglong2*)(shx + jl * DDIM);
            unsigned long long a0 = 0ULL, a1 = 0ULL, a2 = 0ULL, a3 = 0ULL;
            #pragma unroll
            for (int q = 0; q < 16; q++) {
                ulonglong2 v = row[q];                       // LDS.128 broadcast
                unsigned long long d0 = fadd2(xi[2 * q],     v.x) & ABS2;
                unsigned long long d1 = fadd2(xi[2 * q + 1], v.y) & ABS2;
                if (q & 1) { a2 = fadd2(a2, d0); a3 = fadd2(a3, d1); }
                else       { a0 = fadd2(a0, d0); a1 = fadd2(a1, d1); }
            }
            unsigned long long s01 = fadd2(a0, a1);
            unsigned long long s23 = fadd2(a2, a3);
            unsigned long long sAll = fadd2(s01, s23);
            float2 f2 = *(float2*)&sAll;
            float dist = f2.x + f2.y;

            if (shl[jl] == myl) sp += dist;
            else                sn += frcp(dist + EPSV);
        }
    }

    // One exclusive slot per (i, chunk): plain stores, no atomics, deterministic.
    g_spos[i * JCHUNKS + blockIdx.y] = sp;
    g_sneg[i * JCHUNKS + blockIdx.y] = sn;
}

__global__ void ecstfl_finalize_kernel(const int* __restrict__ lab,
                                       float* __restrict__ out) {
    __shared__ float red[256];
    float s = 0.0f;
    for (int i = threadIdx.x; i < NROWS; i += 256) {
        float sp = 0.0f, sn = 0.0f;
        #pragma unroll
        for (int c = 0; c < JCHUNKS; c++) {   // fixed order -> deterministic
            sp += g_spos[i * JCHUNKS + c];
            sn += g_sneg[i * JCHUNKS + c];
        }
        float cp  = (float)g_cnt[lab[i]];                 // same-label count incl. self
        float att = sp / (cp + EPSV);                     // (cnt-1)+1+eps == cnt+eps
        float rep = sn / ((float)NROWS - cp + 1.0f + EPSV);
        s += att * rep;
    }
    red[threadIdx.x] = s;
    __syncthreads();
    for (int o = 128; o > 0; o >>= 1) {
        if (threadIdx.x < o) red[threadIdx.x] += red[threadIdx.x + o];
        __syncthreads();
    }
    if (threadIdx.x == 0)
        out[0] = red[0] / ((float)NROWS * (float)NROWS);  // mean(att*rep/N)
}

extern "C" void kernel_launch(void* const* d_in, const int* in_sizes, int n_in,
                              void* d_out, int out_size) {
    (void)in_sizes; (void)n_in; (void)out_size;
    const float* X   = (const float*)d_in[0];
    const int*   lab = (const int*)d_in[1];
    float* out = (float*)d_out;

    // Separate launches give the required ordering (zero -> count) on a stream;
    // grid-launch ordering within the captured graph preserves dependencies.
    ecstfl_count_kernel<<<1, 128>>>(lab);
    ecstfl_count2_kernel<<<(NROWS + 255) / 256, 256>>>(lab);
    ecstfl_main_kernel<<<dim3(NROWS / TI, JCHUNKS), TI>>>(X, lab);
    ecstfl_finalize_kernel<<<1, 256>>>(lab, out);
}

// round 3
// speedup vs baseline: 1.1942x; 1.1942x over previous
#include <cuda_runtime.h>
#include <cuda_bf16.h>
#include <cstdint>

#define NROWS 8192
#define DDIM  64
#define NCLS  100
#define EPSV  1e-6f

#define TI 128        // threads per block == i-rows per block
#define TJ 128        // j rows staged in shared per tile
#define JCHUNKS 16    // j-range splits (grid.y)
#define JPER (NROWS / JCHUNKS)   // 512

#define FBLOCKS 64    // finalize stage-1 blocks (128 rows each)

// Scratch (device globals; no allocation allowed).
// Partials are written exactly once per (i, chunk) -> fully deterministic.
__device__ float g_spos[NROWS * JCHUNKS];
__device__ float g_sneg[NROWS * JCHUNKS];
__device__ int   g_cnt[NCLS];
__device__ float g_part[FBLOCKS];

static __device__ __forceinline__ unsigned long long fadd2(unsigned long long a,
                                                           unsigned long long b) {
    unsigned long long r;
    asm("add.rn.f32x2 %0, %1, %2;" : "=l"(r) : "l"(a), "l"(b));
    return r;
}

static __device__ __forceinline__ float frcp(float x) {
    float r;
    asm("rcp.approx.f32 %0, %1;" : "=f"(r) : "f"(x));
    return r;
}

__global__ void ecstfl_cntzero_kernel() {
    if (threadIdx.x < NCLS) g_cnt[threadIdx.x] = 0;
}

__global__ void ecstfl_count_kernel(const int* __restrict__ lab) {
    int t = blockIdx.x * blockDim.x + threadIdx.x;
    if (t < NROWS) atomicAdd(&g_cnt[lab[t]], 1);   // int atomics: order-invariant
}

__global__ void __launch_bounds__(TI, 4)
ecstfl_main_kernel(const float* __restrict__ X, const int* __restrict__ lab) {
    __shared__ float shx[TJ * DDIM];   // negated x_j tile
    __shared__ int   shl[TJ];

    const int i  = blockIdx.x * TI + threadIdx.x;
    const int j0 = blockIdx.y * JPER;

    // Load my row x_i into registers as 32 packed f32x2 values.
    unsigned long long xi[DDIM / 2];
    {
        const ulonglong2* xrow = (const ulonglong2*)(X + (size_t)i * DDIM);
        #pragma unroll
        for (int q = 0; q < DDIM / 4; q++) {
            ulonglong2 v = xrow[q];
            xi[2 * q]     = v.x;
            xi[2 * q + 1] = v.y;
        }
    }
    const int myl = lab[i];

    const unsigned long long ABS2 = 0x7FFFFFFF7FFFFFFFULL;

    float sp = 0.0f;   // sum of dist over same-label j in this chunk
    float sn = 0.0f;   // sum of 1/(dist+eps) over diff-label j in this chunk

    #pragma unroll 1
    for (int t = 0; t < JPER / TJ; t++) {
        const int jt = j0 + t * TJ;

        __syncthreads();   // protect previous tile from overwrite

        // Stage TJ*DDIM floats (negated) cooperatively: 16 float4 per thread.
        {
            const float4* src = (const float4*)(X + (size_t)jt * DDIM);
            float4* dst = (float4*)shx;
            #pragma unroll
            for (int r = 0; r < (TJ * DDIM / 4) / TI; r++) {
                float4 v = src[threadIdx.x + r * TI];
                v.x = -v.x; v.y = -v.y; v.z = -v.z; v.w = -v.w;
                dst[threadIdx.x + r * TI] = v;
            }
            if (threadIdx.x < TJ) shl[threadIdx.x] = lab[jt + threadIdx.x];
        }
        __syncthreads();

        #pragma unroll 4
        for (int jl = 0; jl < TJ; jl++) {
            const ulonglong2* row = (const ulonglong2*)(shx + jl * DDIM);
            unsigned long long a0 = 0ULL, a1 = 0ULL, a2 = 0ULL, a3 = 0ULL;
            #pragma unroll
            for (int q = 0; q < 16; q++) {
                ulonglong2 v = row[q];                       // LDS.128 broadcast
                unsigned long long d0 = fadd2(xi[2 * q],     v.x) & ABS2;
                unsigned long long d1 = fadd2(xi[2 * q + 1], v.y) & ABS2;
                if (q & 1) { a2 = fadd2(a2, d0); a3 = fadd2(a3, d1); }
                else       { a0 = fadd2(a0, d0); a1 = fadd2(a1, d1); }
            }
            unsigned long long s01 = fadd2(a0, a1);
            unsigned long long s23 = fadd2(a2, a3);
            unsigned long long sAll = fadd2(s01, s23);
            float2 f2 = *(float2*)&sAll;
            float dist = f2.x + f2.y;

            // Branchless (warp-divergence-free): always compute rcp, mask with
            // selects. MUFU is 1 issue/warp-j, far below the binding pipes.
            float r = frcp(dist + EPSV);
            bool  m = (shl[jl] == myl);
            sp += m ? dist : 0.0f;
            sn += m ? 0.0f : r;
        }
    }

    // One exclusive slot per (i, chunk): plain stores, no atomics, deterministic.
    g_spos[i * JCHUNKS + blockIdx.y] = sp;
    g_sneg[i * JCHUNKS + blockIdx.y] = sn;
}

// Finalize stage 1: 64 blocks x 128 threads, one row per thread, block-reduce.
__global__ void __launch_bounds__(128)
ecstfl_final1_kernel(const int* __restrict__ lab) {
    __shared__ float red[128];
    const int i = blockIdx.x * 128 + threadIdx.x;

    float sp = 0.0f, sn = 0.0f;
    #pragma unroll
    for (int c = 0; c < JCHUNKS; c++) {        // fixed order -> deterministic
        sp += g_spos[i * JCHUNKS + c];
        sn += g_sneg[i * JCHUNKS + c];
    }
    float cp  = (float)g_cnt[lab[i]];          // same-label count incl. self
    float att = sp / (cp + EPSV);              // (cnt-1)+1+eps == cnt+eps
    float rep = sn / ((float)NROWS - cp + 1.0f + EPSV);
    red[threadIdx.x] = att * rep;
    __syncthreads();
    #pragma unroll
    for (int o = 64; o > 0; o >>= 1) {         // fixed tree -> deterministic
        if (threadIdx.x < o) red[threadIdx.x] += red[threadIdx.x + o];
        __syncthreads();
    }
    if (threadIdx.x == 0) g_part[blockIdx.x] = red[0];
}

// Finalize stage 2: one block sums the 64 partials in a fixed tree.
__global__ void ecstfl_final2_kernel(float* __restrict__ out) {
    __shared__ float red[FBLOCKS];
    red[threadIdx.x] = g_part[threadIdx.x];
    __syncthreads();
    #pragma unroll
    for (int o = FBLOCKS / 2; o > 0; o >>= 1) {
        if (threadIdx.x < o) red[threadIdx.x] += red[threadIdx.x + o];
        __syncthreads();
    }
    if (threadIdx.x == 0)
        out[0] = red[0] / ((float)NROWS * (float)NROWS);   // mean(att*rep/N)
}

extern "C" void kernel_launch(void* const* d_in, const int* in_sizes, int n_in,
                              void* d_out, int out_size) {
    (void)in_sizes; (void)n_in; (void)out_size;
    const float* X   = (const float*)d_in[0];
    const int*   lab = (const int*)d_in[1];
    float* out = (float*)d_out;

    ecstfl_cntzero_kernel<<<1, 128>>>();
    ecstfl_count_kernel<<<(NROWS + 255) / 256, 256>>>(lab);
    ecstfl_main_kernel<<<dim3(NROWS / TI, JCHUNKS), TI>>>(X, lab);
    ecstfl_final1_kernel<<<FBLOCKS, 128>>>(lab);
    ecstfl_final2_kernel<<<1, FBLOCKS>>>(out);
}

// round 4
// speedup vs baseline: 1.6784x; 1.4055x over previous
#include <cuda_runtime.h>
#include <cuda_bf16.h>
#include <cstdint>
#include <cmath>

#define NROWS 8192
#define DDIM  64
#define NCLS  100
#define EPSV  1e-6f

#define TI 128                 // threads per block == rows per I-block
#define NB (NROWS / TI)        // 64 row-blocks
#define NTILES (NB * (NB + 1) / 2)   // 2080 upper-tri tiles
#define FBLOCKS 64

// Scratch (device globals; no allocation allowed).
// g_srow/g_snrow: slot [i][t] has exactly ONE writer each replay:
//   t >= bi(i): row-part of tile (bi, t);  t < bi(i): transposed part of tile (t, bi).
// -> fully deterministic, no float atomics, no zero-init needed.
__device__ float g_srow[NROWS * NB];
__device__ float g_snrow[NROWS * NB];
__device__ int   g_cnt[NCLS];
__device__ float g_part[FBLOCKS];

static __device__ __forceinline__ unsigned long long fadd2(unsigned long long a,
                                                           unsigned long long b) {
    unsigned long long r;
    asm("add.rn.f32x2 %0, %1, %2;" : "=l"(r) : "l"(a), "l"(b));
    return r;
}

static __device__ __forceinline__ float frcp(float x) {
    float r;
    asm("rcp.approx.f32 %0, %1;" : "=f"(r) : "f"(x));
    return r;
}

__global__ void __launch_bounds__(TI, 4)
ecstfl_main_kernel(const float* __restrict__ X, const int* __restrict__ lab) {
    __shared__ float shx[TI * DDIM];      // negated x_j tile (32 KB)
    __shared__ int   shl[TI];
    __shared__ float cps[4][TI];          // per-warp column partials (sp)
    __shared__ float cns[4][TI];          // per-warp column partials (sn)

    // Decode upper-triangular tile (bi <= bj) from linear block index.
    const int t = blockIdx.x;
    int bi = (int)(64.5f - sqrtf(64.5f * 64.5f - 2.0f * (float)t));
    while (bi > 0 && bi * NB - bi * (bi - 1) / 2 > t) bi--;
    while ((bi + 1) * NB - (bi + 1) * bi / 2 <= t) bi++;
    const int bj = bi + (t - (bi * NB - bi * (bi - 1) / 2));
    const bool diag = (bi == bj);

    const int i  = bi * TI + threadIdx.x;
    const int J0 = bj * TI;
    const int w    = threadIdx.x >> 5;
    const int lane = threadIdx.x & 31;

    // Load my row x_i into registers as 32 packed f32x2 values.
    unsigned long long xi[DDIM / 2];
    {
        const ulonglong2* xrow = (const ulonglong2*)(X + (size_t)i * DDIM);
        #pragma unroll
        for (int q = 0; q < DDIM / 4; q++) {
            ulonglong2 v = xrow[q];
            xi[2 * q]     = v.x;
            xi[2 * q + 1] = v.y;
        }
    }
    const int myl = lab[i];

    // Stage J tile (negated) cooperatively: 16 float4 per thread.
    {
        const float4* src = (const float4*)(X + (size_t)J0 * DDIM);
        float4* dst = (float4*)shx;
        #pragma unroll
        for (int r = 0; r < (TI * DDIM / 4) / TI; r++) {
            float4 v = src[threadIdx.x + r * TI];
            v.x = -v.x; v.y = -v.y; v.z = -v.z; v.w = -v.w;
            dst[threadIdx.x + r * TI] = v;
        }
        shl[threadIdx.x] = lab[J0 + threadIdx.x];
    }
    __syncthreads();

    const unsigned long long ABS2 = 0x7FFFFFFF7FFFFFFFULL;

    float sp = 0.0f;   // row-sum of dist over same-label j in this tile
    float sn = 0.0f;   // row-sum of 1/(dist+eps) over diff-label j

    if (!diag) {
        #pragma unroll 2
        for (int jl = 0; jl < TI; jl++) {
            const ulonglong2* row = (const ulonglong2*)(shx + jl * DDIM);
            unsigned long long a0 = 0ULL, a1 = 0ULL, a2 = 0ULL, a3 = 0ULL;
            #pragma unroll
            for (int q = 0; q < 16; q++) {
                ulonglong2 v = row[q];                      // LDS.128 broadcast
                unsigned long long d0 = fadd2(xi[2 * q],     v.x) & ABS2;
                unsigned long long d1 = fadd2(xi[2 * q + 1], v.y) & ABS2;
                if (q & 1) { a2 = fadd2(a2, d0); a3 = fadd2(a3, d1); }
                else       { a0 = fadd2(a0, d0); a1 = fadd2(a1, d1); }
            }
            unsigned long long sAll = fadd2(fadd2(a0, a1), fadd2(a2, a3));
            float2 f2 = *(float2*)&sAll;
            float dist = f2.x + f2.y;

            float r  = frcp(dist + EPSV);
            bool  m  = (shl[jl] == myl);
            float vsp = m ? dist : 0.0f;
            float vsn = m ? 0.0f : r;
            sp += vsp;
            sn += vsn;

            // Symmetric credit: butterfly-sum this j's contributions from the
            // 32 lanes (32 distinct i), lane 0 stores the warp partial.
            #pragma unroll
            for (int o = 16; o > 0; o >>= 1) {
                vsp += __shfl_xor_sync(0xFFFFFFFFu, vsp, o);
                vsn += __shfl_xor_sync(0xFFFFFFFFu, vsn, o);
            }
            if (lane == 0) { cps[w][jl] = vsp; cns[w][jl] = vsn; }
        }
    } else {
        #pragma unroll 2
        for (int jl = 0; jl < TI; jl++) {
            const ulonglong2* row = (const ulonglong2*)(shx + jl * DDIM);
            unsigned long long a0 = 0ULL, a1 = 0ULL, a2 = 0ULL, a3 = 0ULL;
            #pragma unroll
            for (int q = 0; q < 16; q++) {
                ulonglong2 v = row[q];
                unsigned long long d0 = fadd2(xi[2 * q],     v.x) & ABS2;
                unsigned long long d1 = fadd2(xi[2 * q + 1], v.y) & ABS2;
                if (q & 1) { a2 = fadd2(a2, d0); a3 = fadd2(a3, d1); }
                else       { a0 = fadd2(a0, d0); a1 = fadd2(a1, d1); }
            }
            unsigned long long sAll = fadd2(fadd2(a0, a1), fadd2(a2, a3));
            float2 f2 = *(float2*)&sAll;
            float dist = f2.x + f2.y;

            float r  = frcp(dist + EPSV);
            bool  m  = (shl[jl] == myl);
            sp += m ? dist : 0.0f;      // self-pair: dist=0 contributes 0
            sn += m ? 0.0f : r;
        }
    }

    // Row part: unique slot [i][bj].
    g_srow [i * NB + bj] = sp;
    g_snrow[i * NB + bj] = sn;

    if (!diag) {
        __syncthreads();
        // Merge 4 warp partials for column j = J0 + tid (fixed order) and
        // write the transposed part into unique slot [j][bi].
        const int jg = J0 + threadIdx.x;
        float csp = ((cps[0][threadIdx.x] + cps[1][threadIdx.x]) +
                     (cps[2][threadIdx.x] + cps[3][threadIdx.x]));
        float csn = ((cns[0][threadIdx.x] + cns[1][threadIdx.x]) +
                     (cns[2][threadIdx.x] + cns[3][threadIdx.x]));
        g_srow [jg * NB + bi] = csp;
        g_snrow[jg * NB + bi] = csn;
    }
}

__global__ void ecstfl_cntzero_kernel() {
    if (threadIdx.x < NCLS) g_cnt[threadIdx.x] = 0;
}

__global__ void ecstfl_count_kernel(const int* __restrict__ lab) {
    int t = blockIdx.x * blockDim.x + threadIdx.x;
    if (t < NROWS) atomicAdd(&g_cnt[lab[t]], 1);   // int atomics: order-invariant
}

// Finalize stage 1: 64 blocks x 128 threads, one row per thread, block-reduce.
__global__ void __launch_bounds__(128)
ecstfl_final1_kernel(const int* __restrict__ lab) {
    __shared__ float red[128];
    const int i = blockIdx.x * 128 + threadIdx.x;

    float sp = 0.0f, sn = 0.0f;
    #pragma unroll
    for (int c = 0; c < NB; c++) {             // fixed order -> deterministic
        sp += g_srow [i * NB + c];
        sn += g_snrow[i * NB + c];
    }
    float cp  = (float)g_cnt[lab[i]];          // same-label count incl. self
    float att = sp / (cp + EPSV);              // (cnt-1)+1+eps == cnt+eps
    float rep = sn / ((float)NROWS - cp + 1.0f + EPSV);
    red[threadIdx.x] = att * rep;
    __syncthreads();
    #pragma unroll
    for (int o = 64; o > 0; o >>= 1) {
        if (threadIdx.x < o) red[threadIdx.x] += red[threadIdx.x + o];
        __syncthreads();
    }
    if (threadIdx.x == 0) g_part[blockIdx.x] = red[0];
}

__global__ void ecstfl_final2_kernel(float* __restrict__ out) {
    __shared__ float red[FBLOCKS];
    red[threadIdx.x] = g_part[threadIdx.x];
    __syncthreads();
    #pragma unroll
    for (int o = FBLOCKS / 2; o > 0; o >>= 1) {
        if (threadIdx.x < o) red[threadIdx.x] += red[threadIdx.x + o];
        __syncthreads();
    }
    if (threadIdx.x == 0)
        out[0] = red[0] / ((float)NROWS * (float)NROWS);   // mean(att*rep/N)
}

extern "C" void kernel_launch(void* const* d_in, const int* in_sizes, int n_in,
                              void* d_out, int out_size) {
    (void)in_sizes; (void)n_in; (void)out_size;
    const float* X   = (const float*)d_in[0];
    const int*   lab = (const int*)d_in[1];
    float* out = (float*)d_out;

    // Main first (no dependency on counts) so ncu's launch-skip lands on it.
    ecstfl_main_kernel<<<NTILES, TI>>>(X, lab);
    ecstfl_cntzero_kernel<<<1, 128>>>();
    ecstfl_count_kernel<<<(NROWS + 255) / 256, 256>>>(lab);
    ecstfl_final1_kernel<<<FBLOCKS, 128>>>(lab);
    ecstfl_final2_kernel<<<1, FBLOCKS>>>(out);
}

// round 5
// speedup vs baseline: 1.7364x; 1.0346x over previous
#include <cuda_runtime.h>
#include <cuda_bf16.h>
#include <cstdint>
#include <cmath>

#define NROWS 8192
#define DDIM  64
#define NCLS  100
#define EPSV  1e-6f

#define TB   64                 // threads per block (2 warps)
#define TILE 128                // tile edge: 128 i-rows x 128 j-rows
#define NB   (NROWS / TILE)     // 64 row-blocks
#define NTILES (NB * (NB + 1) / 2)   // 2080 upper-tri tiles
#define FBLOCKS 64

// Scratch (device globals; no allocation allowed).
// Layout [slot][row]: coalesced STG from main, coalesced LDG in final1.
// Every slot has exactly ONE writer per replay -> deterministic, no atomics.
__device__ float g_srow [NB * NROWS];
__device__ float g_snrow[NB * NROWS];
__device__ int   g_cnt[NCLS];
__device__ float g_part[FBLOCKS];

static __device__ __forceinline__ unsigned long long fadd2(unsigned long long a,
                                                           unsigned long long b) {
    unsigned long long r;
    asm("add.rn.f32x2 %0, %1, %2;" : "=l"(r) : "l"(a), "l"(b));
    return r;
}

static __device__ __forceinline__ float frcp(float x) {
    float r;
    asm("rcp.approx.f32 %0, %1;" : "=f"(r) : "f"(x));
    return r;
}

__global__ void __launch_bounds__(TB, 5)
ecstfl_main_kernel(const float* __restrict__ X, const int* __restrict__ lab) {
    __shared__ float shx[TILE * DDIM];                 // negated x_j tile (32 KB)
    __shared__ int   shl[TILE];
    __shared__ unsigned long long cpn[2][TILE];        // per-warp packed col partials

    // Decode upper-triangular tile (bi <= bj) from linear block index.
    const int t = blockIdx.x;
    int bi = (int)(64.5f - sqrtf(64.5f * 64.5f - 2.0f * (float)t));
    while (bi > 0 && bi * NB - bi * (bi - 1) / 2 > t) bi--;
    while ((bi + 1) * NB - (bi + 1) * bi / 2 <= t) bi++;
    const int bj = bi + (t - (bi * NB - bi * (bi - 1) / 2));
    const bool diag = (bi == bj);

    const int tid  = threadIdx.x;
    const int w    = tid >> 5;
    const int lane = tid & 31;
    const int i0   = bi * TILE + tid;      // first owned row
    const int i1   = i0 + TB;              // second owned row
    const int J0   = bj * TILE;

    // Two rows of x_i in registers (32 packed f32x2 each).
    unsigned long long xiA[DDIM / 2], xiB[DDIM / 2];
    {
        const ulonglong2* ra = (const ulonglong2*)(X + (size_t)i0 * DDIM);
        const ulonglong2* rb = (const ulonglong2*)(X + (size_t)i1 * DDIM);
        #pragma unroll
        for (int q = 0; q < DDIM / 4; q++) {
            ulonglong2 va = ra[q];  xiA[2 * q] = va.x;  xiA[2 * q + 1] = va.y;
            ulonglong2 vb = rb[q];  xiB[2 * q] = vb.x;  xiB[2 * q + 1] = vb.y;
        }
    }
    const int lA = lab[i0];
    const int lB = lab[i1];

    // Stage J tile (negated) cooperatively: 32 float4 per thread.
    {
        const float4* src = (const float4*)(X + (size_t)J0 * DDIM);
        float4* dst = (float4*)shx;
        #pragma unroll
        for (int r = 0; r < (TILE * DDIM / 4) / TB; r++) {
            float4 v = src[tid + r * TB];
            v.x = -v.x; v.y = -v.y; v.z = -v.z; v.w = -v.w;
            dst[tid + r * TB] = v;
        }
        shl[tid]      = lab[J0 + tid];
        shl[tid + TB] = lab[J0 + tid + TB];
    }
    __syncthreads();

    const unsigned long long ABS2 = 0x7FFFFFFF7FFFFFFFULL;

    float spA = 0.0f, snA = 0.0f, spB = 0.0f, snB = 0.0f;

    #pragma unroll 1
    for (int jl = 0; jl < TILE; jl++) {
        const ulonglong2* row = (const ulonglong2*)(shx + jl * DDIM);
        unsigned long long a0 = 0ULL, a1 = 0ULL, b0 = 0ULL, b1 = 0ULL;
        #pragma unroll
        for (int q = 0; q < 16; q++) {
            ulonglong2 v = row[q];                       // LDS.128 broadcast
            unsigned long long dA0 = fadd2(xiA[2 * q],     v.x) & ABS2;
            unsigned long long dB0 = fadd2(xiB[2 * q],     v.x) & ABS2;
            unsigned long long dA1 = fadd2(xiA[2 * q + 1], v.y) & ABS2;
            unsigned long long dB1 = fadd2(xiB[2 * q + 1], v.y) & ABS2;
            a0 = fadd2(a0, dA0);  b0 = fadd2(b0, dB0);
            a1 = fadd2(a1, dA1);  b1 = fadd2(b1, dB1);
        }
        unsigned long long sA = fadd2(a0, a1);
        unsigned long long sB = fadd2(b0, b1);
        float2 fA = *(float2*)&sA;
        float2 fB = *(float2*)&sB;
        float distA = fA.x + fA.y;
        float distB = fB.x + fB.y;

        float rA = frcp(distA + EPSV);
        float rB = frcp(distB + EPSV);
        int   jlab = shl[jl];
        bool  mA = (jlab == lA);
        bool  mB = (jlab == lB);
        float cspA = mA ? distA : 0.0f;
        float csnA = mA ? 0.0f  : rA;
        float cspB = mB ? distB : 0.0f;
        float csnB = mB ? 0.0f  : rB;
        spA += cspA;  snA += csnA;
        spB += cspB;  snB += csnB;

        if (!diag) {
            // Symmetric credit: one packed butterfly covers both owned rows.
            float bsp = cspA + cspB;
            float bsn = csnA + csnB;
            unsigned long long pv;
            asm("mov.b64 %0, {%1, %2};" : "=l"(pv) : "f"(bsp), "f"(bsn));
            #pragma unroll
            for (int o = 16; o > 0; o >>= 1) {
                unsigned long long qv = __shfl_xor_sync(0xFFFFFFFFu, pv, o);
                pv = fadd2(pv, qv);
            }
            if (lane == 0) cpn[w][jl] = pv;
        }
    }

    // Row parts: unique slots [bj][i0], [bj][i1] (coalesced STG).
    g_srow [bj * NROWS + i0] = spA;
    g_snrow[bj * NROWS + i0] = snA;
    g_srow [bj * NROWS + i1] = spB;
    g_snrow[bj * NROWS + i1] = snB;

    if (!diag) {
        __syncthreads();
        // Merge the 2 warp partials per column (fixed order) and write the
        // transposed credit into unique slots [bi][j] (coalesced STG).
        #pragma unroll
        for (int h = 0; h < 2; h++) {
            int c = tid + h * TB;
            unsigned long long pv = fadd2(cpn[0][c], cpn[1][c]);
            float csp, csn;
            asm("mov.b64 {%0, %1}, %2;" : "=f"(csp), "=f"(csn) : "l"(pv));
            int j = J0 + c;
            g_srow [bi * NROWS + j] = csp;
            g_snrow[bi * NROWS + j] = csn;
        }
    }
}

__global__ void ecstfl_cntzero_kernel() {
    if (threadIdx.x < NCLS) g_cnt[threadIdx.x] = 0;
}

__global__ void ecstfl_count_kernel(const int* __restrict__ lab) {
    int t = blockIdx.x * blockDim.x + threadIdx.x;
    if (t < NROWS) atomicAdd(&g_cnt[lab[t]], 1);   // int atomics: order-invariant
}

// Finalize stage 1: 64 blocks x 128 threads; [slot][row] layout -> coalesced.
__global__ void __launch_bounds__(128)
ecstfl_final1_kernel(const int* __restrict__ lab) {
    __shared__ float red[128];
    const int i = blockIdx.x * 128 + threadIdx.x;

    float sp = 0.0f, sn = 0.0f;
    #pragma unroll
    for (int c = 0; c < NB; c++) {             // fixed order -> deterministic
        sp += g_srow [c * NROWS + i];
        sn += g_snrow[c * NROWS + i];
    }
    float cp  = (float)g_cnt[lab[i]];          // same-label count incl. self
    float att = sp / (cp + EPSV);              // (cnt-1)+1+eps == cnt+eps
    float rep = sn / ((float)NROWS - cp + 1.0f + EPSV);
    red[threadIdx.x] = att * rep;
    __syncthreads();
    #pragma unroll
    for (int o = 64; o > 0; o >>= 1) {
        if (threadIdx.x < o) red[threadIdx.x] += red[threadIdx.x + o];
        __syncthreads();
    }
    if (threadIdx.x == 0) g_part[blockIdx.x] = red[0];
}

__global__ void ecstfl_final2_kernel(float* __restrict__ out) {
    __shared__ float red[FBLOCKS];
    red[threadIdx.x] = g_part[threadIdx.x];
    __syncthreads();
    #pragma unroll
    for (int o = FBLOCKS / 2; o > 0; o >>= 1) {
        if (threadIdx.x < o) red[threadIdx.x] += red[threadIdx.x + o];
        __syncthreads();
    }
    if (threadIdx.x == 0)
        out[0] = red[0] / ((float)NROWS * (float)NROWS);   // mean(att*rep/N)
}

extern "C" void kernel_launch(void* const* d_in, const int* in_sizes, int n_in,
                              void* d_out, int out_size) {
    (void)in_sizes; (void)n_in; (void)out_size;
    const float* X   = (const float*)d_in[0];
    const int*   lab = (const int*)d_in[1];
    float* out = (float*)d_out;

    ecstfl_main_kernel<<<NTILES, TB>>>(X, lab);
    ecstfl_cntzero_kernel<<<1, 128>>>();
    ecstfl_count_kernel<<<(NROWS + 255) / 256, 256>>>(lab);
    ecstfl_final1_kernel<<<FBLOCKS, 128>>>(lab);
    ecstfl_final2_kernel<<<1, FBLOCKS>>>(out);
}

// round 6
// speedup vs baseline: 2.0030x; 1.1535x over previous
#include <cuda_runtime.h>
#include <cuda_bf16.h>
#include <cstdint>
#include <cmath>

#define NROWS 8192
#define DDIM  64
#define NCLS  100
#define EPSV  1e-6f

#define TB   64                 // threads per block (2 warps)
#define TILE 128                // tile edge: 128 i-rows x 128 j-rows
#define NB   (NROWS / TILE)     // 64 row-blocks
#define NTILES (NB * (NB + 1) / 2)   // 2080 upper-tri tiles
#define FBLOCKS 64

// Scratch (device globals; no allocation allowed).
// Layout [slot][row]: coalesced STG from main, coalesced LDG in final1.
// Every slot has exactly ONE writer per replay -> deterministic, no atomics.
__device__ float g_srow [NB * NROWS];
__device__ float g_snrow[NB * NROWS];
__device__ int   g_cnt[NCLS];
__device__ float g_part[FBLOCKS];

static __device__ __forceinline__ unsigned long long fadd2(unsigned long long a,
                                                           unsigned long long b) {
    unsigned long long r;
    asm("add.rn.f32x2 %0, %1, %2;" : "=l"(r) : "l"(a), "l"(b));
    return r;
}

static __device__ __forceinline__ float frcp(float x) {
    float r;
    asm("rcp.approx.f32 %0, %1;" : "=f"(r) : "f"(x));
    return r;
}

__global__ void __launch_bounds__(TB, 5)
ecstfl_main_kernel(const float* __restrict__ X, const int* __restrict__ lab) {
    __shared__ float shx[TILE * DDIM];                 // -x_j/2 tile (32 KB)
    __shared__ int   shl[TILE];
    __shared__ unsigned long long cpn[2][TILE];        // per-warp packed col partials

    // Decode upper-triangular tile (bi <= bj) from linear block index.
    const int t = blockIdx.x;
    int bi = (int)(64.5f - sqrtf(64.5f * 64.5f - 2.0f * (float)t));
    while (bi > 0 && bi * NB - bi * (bi - 1) / 2 > t) bi--;
    while ((bi + 1) * NB - (bi + 1) * bi / 2 <= t) bi++;
    const int bj = bi + (t - (bi * NB - bi * (bi - 1) / 2));
    const bool diag = (bi == bj);

    const int tid  = threadIdx.x;
    const int w    = tid >> 5;
    const int lane = tid & 31;
    const int i0   = bi * TILE + tid;      // first owned row
    const int i1   = i0 + TB;              // second owned row
    const int J0   = bj * TILE;

    // Two rows of x_i in registers (raw scale).
    float xiA[DDIM], xiB[DDIM];
    {
        const float4* ra = (const float4*)(X + (size_t)i0 * DDIM);
        const float4* rb = (const float4*)(X + (size_t)i1 * DDIM);
        #pragma unroll
        for (int q = 0; q < DDIM / 4; q++) {
            float4 va = ra[q];
            xiA[4*q] = va.x; xiA[4*q+1] = va.y; xiA[4*q+2] = va.z; xiA[4*q+3] = va.w;
            float4 vb = rb[q];
            xiB[4*q] = vb.x; xiB[4*q+1] = vb.y; xiB[4*q+2] = vb.z; xiB[4*q+3] = vb.w;
        }
    }
    const int lA = lab[i0];
    const int lB = lab[i1];

    // Stage J tile as -x_j/2 (power-of-2 exact): 32 float4 per thread.
    {
        const float4* src = (const float4*)(X + (size_t)J0 * DDIM);
        float4* dst = (float4*)shx;
        #pragma unroll
        for (int r = 0; r < (TILE * DDIM / 4) / TB; r++) {
            float4 v = src[tid + r * TB];
            v.x *= -0.5f; v.y *= -0.5f; v.z *= -0.5f; v.w *= -0.5f;
            dst[tid + r * TB] = v;
        }
        shl[tid]      = lab[J0 + tid];
        shl[tid + TB] = lab[J0 + tid + TB];
    }
    __syncthreads();

    float spA = 0.0f, snA = 0.0f, spB = 0.0f, snB = 0.0f;

    #pragma unroll 1
    for (int jl = 0; jl < TILE; jl++) {
        const float4* row = (const float4*)(shx + jl * DDIM);
        // 4 independent accumulator chains (2 per row) of FFMA-imm (rt 1).
        float aA0 = 0.0f, aA1 = 0.0f, aB0 = 0.0f, aB1 = 0.0f;
        #pragma unroll
        for (int q = 0; q < 16; q++) {
            float4 v = row[q];                          // LDS.128 broadcast
            // d_half = x_i*0.5 + (-x_j/2)  -> FFMA-imm (rt1)
            // acc    = |d_half|*2.0 + acc  -> FFMA-imm (rt1); |.| on alu pipe
            float dA0 = fmaf(xiA[4*q+0], 0.5f, v.x);
            float dA1 = fmaf(xiA[4*q+1], 0.5f, v.y);
            float dA2 = fmaf(xiA[4*q+2], 0.5f, v.z);
            float dA3 = fmaf(xiA[4*q+3], 0.5f, v.w);
            float dB0 = fmaf(xiB[4*q+0], 0.5f, v.x);
            float dB1 = fmaf(xiB[4*q+1], 0.5f, v.y);
            float dB2 = fmaf(xiB[4*q+2], 0.5f, v.z);
            float dB3 = fmaf(xiB[4*q+3], 0.5f, v.w);
            aA0 = fmaf(fabsf(dA0), 2.0f, aA0);
            aA1 = fmaf(fabsf(dA1), 2.0f, aA1);
            aA0 = fmaf(fabsf(dA2), 2.0f, aA0);
            aA1 = fmaf(fabsf(dA3), 2.0f, aA1);
            aB0 = fmaf(fabsf(dB0), 2.0f, aB0);
            aB1 = fmaf(fabsf(dB1), 2.0f, aB1);
            aB0 = fmaf(fabsf(dB2), 2.0f, aB0);
            aB1 = fmaf(fabsf(dB3), 2.0f, aB1);
        }
        float distA = aA0 + aA1;
        float distB = aB0 + aB1;

        float rA = frcp(distA + EPSV);
        float rB = frcp(distB + EPSV);
        int   jlab = shl[jl];
        bool  mA = (jlab == lA);
        bool  mB = (jlab == lB);
        float cspA = mA ? distA : 0.0f;
        float csnA = mA ? 0.0f  : rA;
        float cspB = mB ? distB : 0.0f;
        float csnB = mB ? 0.0f  : rB;
        spA += cspA;  snA += csnA;
        spB += cspB;  snB += csnB;

        if (!diag) {
            // Symmetric credit: one packed butterfly covers both owned rows.
            float bsp = cspA + cspB;
            float bsn = csnA + csnB;
            unsigned long long pv;
            asm("mov.b64 %0, {%1, %2};" : "=l"(pv) : "f"(bsp), "f"(bsn));
            #pragma unroll
            for (int o = 16; o > 0; o >>= 1) {
                unsigned long long qv = __shfl_xor_sync(0xFFFFFFFFu, pv, o);
                pv = fadd2(pv, qv);
            }
            if (lane == 0) cpn[w][jl] = pv;
        }
    }

    // Row parts: unique slots [bj][i0], [bj][i1] (coalesced STG).
    g_srow [bj * NROWS + i0] = spA;
    g_snrow[bj * NROWS + i0] = snA;
    g_srow [bj * NROWS + i1] = spB;
    g_snrow[bj * NROWS + i1] = snB;

    if (!diag) {
        __syncthreads();
        // Merge the 2 warp partials per column (fixed order), transposed slots.
        #pragma unroll
        for (int h = 0; h < 2; h++) {
            int c = tid + h * TB;
            unsigned long long pv = fadd2(cpn[0][c], cpn[1][c]);
            float csp, csn;
            asm("mov.b64 {%0, %1}, %2;" : "=f"(csp), "=f"(csn) : "l"(pv));
            int j = J0 + c;
            g_srow [bi * NROWS + j] = csp;
            g_snrow[bi * NROWS + j] = csn;
        }
    }
}

__global__ void ecstfl_cntzero_kernel() {
    if (threadIdx.x < NCLS) g_cnt[threadIdx.x] = 0;
}

__global__ void ecstfl_count_kernel(const int* __restrict__ lab) {
    int t = blockIdx.x * blockDim.x + threadIdx.x;
    if (t < NROWS) atomicAdd(&g_cnt[lab[t]], 1);   // int atomics: order-invariant
}

// Position-3 filler (also zeroes g_part) so main lands at captured slot 4.
__global__ void ecstfl_partzero_kernel() {
    if (threadIdx.x < FBLOCKS) g_part[threadIdx.x] = 0.0f;
}

// Finalize stage 1: 64 blocks x 128 threads; [slot][row] layout -> coalesced.
__global__ void __launch_bounds__(128)
ecstfl_final1_kernel(const int* __restrict__ lab) {
    __shared__ float red[128];
    const int i = blockIdx.x * 128 + threadIdx.x;

    float sp = 0.0f, sn = 0.0f;
    #pragma unroll
    for (int c = 0; c < NB; c++) {             // fixed order -> deterministic
        sp += g_srow [c * NROWS + i];
        sn += g_snrow[c * NROWS + i];
    }
    float cp  = (float)g_cnt[lab[i]];          // same-label count incl. self
    float att = sp / (cp + EPSV);              // (cnt-1)+1+eps == cnt+eps
    float rep = sn / ((float)NROWS - cp + 1.0f + EPSV);
    red[threadIdx.x] = att * rep;
    __syncthreads();
    #pragma unroll
    for (int o = 64; o > 0; o >>= 1) {
        if (threadIdx.x < o) red[threadIdx.x] += red[threadIdx.x + o];
        __syncthreads();
    }
    if (threadIdx.x == 0) g_part[blockIdx.x] = red[0];
}

__global__ void ecstfl_final2_kernel(float* __restrict__ out) {
    __shared__ float red[FBLOCKS];
    red[threadIdx.x] = g_part[threadIdx.x];
    __syncthreads();
    #pragma unroll
    for (int o = FBLOCKS / 2; o > 0; o >>= 1) {
        if (threadIdx.x < o) red[threadIdx.x] += red[threadIdx.x + o];
        __syncthreads();
    }
    if (threadIdx.x == 0)
        out[0] = red[0] / ((float)NROWS * (float)NROWS);   // mean(att*rep/N)
}

extern "C" void kernel_launch(void* const* d_in, const int* in_sizes, int n_in,
                              void* d_out, int out_size) {
    (void)in_sizes; (void)n_in; (void)out_size;
    const float* X   = (const float*)d_in[0];
    const int*   lab = (const int*)d_in[1];
    float* out = (float*)d_out;

    ecstfl_cntzero_kernel<<<1, 128>>>();                       // pos 1
    ecstfl_count_kernel<<<(NROWS + 255) / 256, 256>>>(lab);    // pos 2
    ecstfl_partzero_kernel<<<1, 64>>>();                       // pos 3 (filler)
    ecstfl_main_kernel<<<NTILES, TB>>>(X, lab);                // pos 4 <- profiled
    ecstfl_final1_kernel<<<FBLOCKS, 128>>>(lab);               // pos 5
    ecstfl_final2_kernel<<<1, FBLOCKS>>>(out);                 // pos 6
}